// round 14
// baseline (speedup 1.0000x reference)
#include <cuda_runtime.h>
#include <math_constants.h>

#define BATCH 16
#define SEQ   577
#define DM    768
#define NH    12
#define DKH   64
#define NP    576   // SEQ - 1 (patch tokens)

// ---------------- scratch (allocation-free per harness rules) ----------------
__device__ float g_Q[BATCH * SEQ * DM];    // Q projection, later reused for FC output
__device__ float g_K[BATCH * SEQ * DM];
__device__ float g_V[BATCH * SEQ * DM];
__device__ float g_att[BATCH * SEQ * DM];  // attention output (head-merged)
__device__ float g_pen[(size_t)BATCH * NP * NP];
__device__ float g_En[(size_t)BATCH * NP * DM];  // normalized embeddings (tf32)

__device__ __forceinline__ unsigned f2tf(float x) {
    unsigned u;
    asm("cvt.rna.tf32.f32 %0, %1;" : "=r"(u) : "f"(x));
    return u;
}
__device__ __forceinline__ float f2tff(float x) { return __uint_as_float(f2tf(x)); }

__device__ __forceinline__ void mma_tf32(float* d, const unsigned* a, const unsigned* b) {
    asm volatile(
        "mma.sync.aligned.m16n8k8.row.col.f32.tf32.tf32.f32 "
        "{%0,%1,%2,%3},{%4,%5,%6,%7},{%8,%9},{%0,%1,%2,%3};"
        : "+f"(d[0]), "+f"(d[1]), "+f"(d[2]), "+f"(d[3])
        : "r"(a[0]), "r"(a[1]), "r"(a[2]), "r"(a[3]), "r"(b[0]), "r"(b[1]));
}

// ---------------- tf32 tensor-core GEMM: C[M,768] = A[M,768] @ W[768,768] -----
__global__ __launch_bounds__(256, 2)
void tgemm_768(const float* __restrict__ A, const float* __restrict__ W,
               float* __restrict__ C, int M) {
    __shared__ float As[128][36];
    __shared__ float Bs[32][132];
    const int tid = threadIdx.x;
    const int wid = tid >> 5, lane = tid & 31;
    const int g = lane >> 2, t4 = lane & 3;
    const int wm = (wid >> 2) * 64, wn = (wid & 3) * 32;
    const int row0 = blockIdx.y * 128, col0 = blockIdx.x * 128;

    float acc[4][4][4] = {};
    const int arow = tid >> 1, acol = (tid & 1) * 16;
    const int brow = tid >> 3, bcol = (tid & 7) * 16;

    for (int k0 = 0; k0 < 768; k0 += 32) {
        const int gr = row0 + arow;
        #pragma unroll
        for (int i = 0; i < 4; i++) {
            float4 v = (gr < M) ? *(const float4*)&A[(size_t)gr * 768 + k0 + acol + i * 4]
                                : make_float4(0.f, 0.f, 0.f, 0.f);
            v.x = f2tff(v.x); v.y = f2tff(v.y); v.z = f2tff(v.z); v.w = f2tff(v.w);
            *(float4*)&As[arow][acol + i * 4] = v;
        }
        #pragma unroll
        for (int i = 0; i < 4; i++) {
            float4 v = *(const float4*)&W[(size_t)(k0 + brow) * 768 + col0 + bcol + i * 4];
            v.x = f2tff(v.x); v.y = f2tff(v.y); v.z = f2tff(v.z); v.w = f2tff(v.w);
            *(float4*)&Bs[brow][bcol + i * 4] = v;
        }
        __syncthreads();

        #pragma unroll
        for (int kk = 0; kk < 32; kk += 8) {
            unsigned af[4][4], bf[4][2];
            #pragma unroll
            for (int mt = 0; mt < 4; mt++) {
                int r = wm + mt * 16;
                af[mt][0] = __float_as_uint(As[r + g][kk + t4]);
                af[mt][1] = __float_as_uint(As[r + g + 8][kk + t4]);
                af[mt][2] = __float_as_uint(As[r + g][kk + t4 + 4]);
                af[mt][3] = __float_as_uint(As[r + g + 8][kk + t4 + 4]);
            }
            #pragma unroll
            for (int nt = 0; nt < 4; nt++) {
                int c = wn + nt * 8;
                bf[nt][0] = __float_as_uint(Bs[kk + t4][c + g]);
                bf[nt][1] = __float_as_uint(Bs[kk + t4 + 4][c + g]);
            }
            #pragma unroll
            for (int mt = 0; mt < 4; mt++)
                #pragma unroll
                for (int nt = 0; nt < 4; nt++)
                    mma_tf32(acc[mt][nt], af[mt], bf[nt]);
        }
        __syncthreads();
    }

    #pragma unroll
    for (int mt = 0; mt < 4; mt++) {
        #pragma unroll
        for (int nt = 0; nt < 4; nt++) {
            int r = row0 + wm + mt * 16 + g;
            int c = col0 + wn + nt * 8 + 2 * t4;
            if (r < M)
                *(float2*)&C[(size_t)r * 768 + c] = make_float2(acc[mt][nt][0], acc[mt][nt][1]);
            if (r + 8 < M)
                *(float2*)&C[(size_t)(r + 8) * 768 + c] = make_float2(acc[mt][nt][2], acc[mt][nt][3]);
        }
    }
}

// ---------------- normalize embedding rows -> tf32 buffer --------------------
__global__ void rnorm_kernel(const float* __restrict__ emb) {
    int b = blockIdx.y, i = blockIdx.x;
    const float* row = emb + (size_t)(b * SEQ + 1 + i) * DM;
    float x[3], s = 0.f;
    #pragma unroll
    for (int t = 0; t < 3; t++) {
        x[t] = row[threadIdx.x + t * 256];
        s += x[t] * x[t];
    }
    __shared__ float red[8];
    #pragma unroll
    for (int o = 16; o; o >>= 1) s += __shfl_xor_sync(0xffffffffu, s, o);
    if ((threadIdx.x & 31) == 0) red[threadIdx.x >> 5] = s;
    __syncthreads();
    __shared__ float srn;
    if (threadIdx.x < 8) {
        float v = red[threadIdx.x];
        #pragma unroll
        for (int o = 4; o; o >>= 1) v += __shfl_xor_sync(0xffu, v, o);
        if (threadIdx.x == 0) srn = rsqrtf(v + 1e-12f);
    }
    __syncthreads();
    float rn = srn;
    float* dst = g_En + (size_t)(b * NP + i) * DM;
    #pragma unroll
    for (int t = 0; t < 3; t++)
        dst[threadIdx.x + t * 256] = f2tff(x[t] * rn);
}

// ---------------- penalty = (En . En^T) * dist, via tf32 MMA -----------------
__global__ __launch_bounds__(256, 2)
void penalty_mma(const float* __restrict__ pos) {
    __shared__ float Es[128][36];
    __shared__ float Fs[128][36];
    const int b = blockIdx.z;
    const int tid = threadIdx.x;
    const int wid = tid >> 5, lane = tid & 31;
    const int g = lane >> 2, t4 = lane & 3;
    const int wm = (wid >> 2) * 64, wn = (wid & 3) * 32;
    const int i0 = blockIdx.y * 128, j0 = blockIdx.x * 128;
    const float* En = g_En + (size_t)b * NP * DM;

    float acc[4][4][4] = {};
    const int lrow = tid >> 1, lcol = (tid & 1) * 16;

    for (int k0 = 0; k0 < 768; k0 += 32) {
        #pragma unroll
        for (int i = 0; i < 4; i++) {
            int ir = i0 + lrow;
            float4 v = (ir < NP) ? *(const float4*)&En[(size_t)ir * 768 + k0 + lcol + i * 4]
                                 : make_float4(0.f, 0.f, 0.f, 0.f);
            *(float4*)&Es[lrow][lcol + i * 4] = v;
            int jr = j0 + lrow;
            float4 w = (jr < NP) ? *(const float4*)&En[(size_t)jr * 768 + k0 + lcol + i * 4]
                                 : make_float4(0.f, 0.f, 0.f, 0.f);
            *(float4*)&Fs[lrow][lcol + i * 4] = w;
        }
        __syncthreads();

        #pragma unroll
        for (int kk = 0; kk < 32; kk += 8) {
            unsigned af[4][4], bf[4][2];
            #pragma unroll
            for (int mt = 0; mt < 4; mt++) {
                int r = wm + mt * 16;
                af[mt][0] = __float_as_uint(Es[r + g][kk + t4]);
                af[mt][1] = __float_as_uint(Es[r + g + 8][kk + t4]);
                af[mt][2] = __float_as_uint(Es[r + g][kk + t4 + 4]);
                af[mt][3] = __float_as_uint(Es[r + g + 8][kk + t4 + 4]);
            }
            #pragma unroll
            for (int nt = 0; nt < 4; nt++) {
                int c = wn + nt * 8;
                bf[nt][0] = __float_as_uint(Fs[c + g][kk + t4]);
                bf[nt][1] = __float_as_uint(Fs[c + g][kk + t4 + 4]);
            }
            #pragma unroll
            for (int mt = 0; mt < 4; mt++)
                #pragma unroll
                for (int nt = 0; nt < 4; nt++)
                    mma_tf32(acc[mt][nt], af[mt], bf[nt]);
        }
        __syncthreads();
    }

    #pragma unroll
    for (int mt = 0; mt < 4; mt++) {
        #pragma unroll
        for (int rr = 0; rr < 2; rr++) {
            int i = i0 + wm + mt * 16 + g + rr * 8;
            if (i >= NP) continue;
            float pix = pos[((size_t)b * NP + i) * 2 + 0];
            float piy = pos[((size_t)b * NP + i) * 2 + 1];
            #pragma unroll
            for (int nt = 0; nt < 4; nt++) {
                #pragma unroll
                for (int cc = 0; cc < 2; cc++) {
                    int j = j0 + wn + nt * 8 + 2 * t4 + cc;
                    if (j >= NP) continue;
                    float dx = pix - pos[((size_t)b * NP + j) * 2 + 0];
                    float dy = piy - pos[((size_t)b * NP + j) * 2 + 1];
                    float dist = sqrtf(dx * dx + dy * dy + 1e-12f);
                    g_pen[((size_t)b * NP + i) * NP + j] = acc[mt][nt][rr * 2 + cc] * dist;
                }
            }
        }
    }
}

// ---------------- tensor-core flash attention with penalty bias --------------
// 4 warps, BM=64 (warp owns 16 rows), BN=64 key tile, D=64.
// KPs holds the K tile, then is reused as the P tile (barrier-protected).
__global__ __launch_bounds__(128)
void attn_mma() {
    __shared__ float KPs[64][68];
    __shared__ float Vs[64][68];

    const int b = blockIdx.z, h = blockIdx.y, i0 = blockIdx.x * 64;
    const int tid = threadIdx.x;
    const int wid = tid >> 5, lane = tid & 31;
    const int g = lane >> 2, t4 = lane & 3;
    const int wm = wid * 16;

    // ---- prologue: stage Q tile in Vs, hoist A-fragments to registers ----
    for (int t = tid; t < 1024; t += 128) {
        int row = t >> 4, c4 = (t & 15) * 4;
        int gi = i0 + row;
        float4 v = make_float4(0.f, 0.f, 0.f, 0.f);
        if (gi < SEQ) v = *(const float4*)&g_Q[(size_t)(b * SEQ + gi) * DM + h * DKH + c4];
        v.x = f2tff(v.x); v.y = f2tff(v.y); v.z = f2tff(v.z); v.w = f2tff(v.w);
        *(float4*)&Vs[row][c4] = v;
    }
    __syncthreads();
    unsigned qf[8][4];
    #pragma unroll
    for (int k8 = 0; k8 < 8; k8++) {
        int kk = k8 * 8;
        qf[k8][0] = __float_as_uint(Vs[wm + g][kk + t4]);
        qf[k8][1] = __float_as_uint(Vs[wm + g + 8][kk + t4]);
        qf[k8][2] = __float_as_uint(Vs[wm + g][kk + t4 + 4]);
        qf[k8][3] = __float_as_uint(Vs[wm + g + 8][kk + t4 + 4]);
    }

    float oacc[8][4] = {};
    float m0 = -CUDART_INF_F, m1 = -CUDART_INF_F, l0 = 0.f, l1 = 0.f;
    const int gi0 = i0 + wm + g, gi1 = gi0 + 8;
    const bool p0 = (gi0 >= 1 && gi0 < SEQ);
    const bool p1 = (gi1 < SEQ);  // gi1 >= 8 always
    const float* pen0 = g_pen + ((size_t)b * NP + (gi0 - 1)) * NP;
    const float* pen1 = g_pen + ((size_t)b * NP + (gi1 - 1)) * NP;

    const int NT = (SEQ + 63) / 64;  // 10
    for (int jt = 0; jt < NT; jt++) {
        const int j0 = jt * 64;
        __syncthreads();  // protect KPs/Vs from previous-iter readers (and qf at jt=0)
        for (int t = tid; t < 1024; t += 128) {
            int row = t >> 4, c4 = (t & 15) * 4;
            int gj = j0 + row;
            float4 kv = make_float4(0.f, 0.f, 0.f, 0.f);
            float4 vv = make_float4(0.f, 0.f, 0.f, 0.f);
            if (gj < SEQ) {
                kv = *(const float4*)&g_K[(size_t)(b * SEQ + gj) * DM + h * DKH + c4];
                vv = *(const float4*)&g_V[(size_t)(b * SEQ + gj) * DM + h * DKH + c4];
            }
            kv.x = f2tff(kv.x); kv.y = f2tff(kv.y); kv.z = f2tff(kv.z); kv.w = f2tff(kv.w);
            vv.x = f2tff(vv.x); vv.y = f2tff(vv.y); vv.z = f2tff(vv.z); vv.w = f2tff(vv.w);
            *(float4*)&KPs[row][c4] = kv;
            *(float4*)&Vs[row][c4] = vv;
        }
        __syncthreads();

        // S = Q . K^T (warp's 16 rows x 64 cols)
        float sacc[8][4] = {};
        #pragma unroll
        for (int k8 = 0; k8 < 8; k8++) {
            int kk = k8 * 8;
            #pragma unroll
            for (int nt = 0; nt < 8; nt++) {
                unsigned bf[2];
                bf[0] = __float_as_uint(KPs[nt * 8 + g][kk + t4]);
                bf[1] = __float_as_uint(KPs[nt * 8 + g][kk + t4 + 4]);
                mma_tf32(sacc[nt], qf[k8], bf);
            }
        }

        // epilogue: scale, penalty, mask; row maxima
        float mloc0 = -CUDART_INF_F, mloc1 = -CUDART_INF_F;
        #pragma unroll
        for (int nt = 0; nt < 8; nt++) {
            #pragma unroll
            for (int cc = 0; cc < 2; cc++) {
                int gj = j0 + nt * 8 + 2 * t4 + cc;
                float v0 = sacc[nt][cc] * 0.125f;
                float v1 = sacc[nt][2 + cc] * 0.125f;
                if (gj >= 1 && gj < SEQ) {
                    if (p0) v0 -= __ldg(&pen0[gj - 1]);
                    if (p1) v1 -= __ldg(&pen1[gj - 1]);
                }
                if (gj >= SEQ) { v0 = -CUDART_INF_F; v1 = -CUDART_INF_F; }
                sacc[nt][cc] = v0; sacc[nt][2 + cc] = v1;
                mloc0 = fmaxf(mloc0, v0); mloc1 = fmaxf(mloc1, v1);
            }
        }
        mloc0 = fmaxf(mloc0, __shfl_xor_sync(0xffffffffu, mloc0, 1));
        mloc0 = fmaxf(mloc0, __shfl_xor_sync(0xffffffffu, mloc0, 2));
        mloc1 = fmaxf(mloc1, __shfl_xor_sync(0xffffffffu, mloc1, 1));
        mloc1 = fmaxf(mloc1, __shfl_xor_sync(0xffffffffu, mloc1, 2));
        float mn0 = fmaxf(m0, mloc0), mn1 = fmaxf(m1, mloc1);
        float sc0 = __expf(m0 - mn0), sc1 = __expf(m1 - mn1);
        m0 = mn0; m1 = mn1;

        float sum0 = 0.f, sum1 = 0.f;
        #pragma unroll
        for (int nt = 0; nt < 8; nt++) {
            #pragma unroll
            for (int cc = 0; cc < 2; cc++) {
                float e0 = __expf(sacc[nt][cc] - m0);
                float e1 = __expf(sacc[nt][2 + cc] - m1);
                sum0 += e0; sum1 += e1;
                sacc[nt][cc] = e0; sacc[nt][2 + cc] = e1;
            }
        }
        sum0 += __shfl_xor_sync(0xffffffffu, sum0, 1);
        sum0 += __shfl_xor_sync(0xffffffffu, sum0, 2);
        sum1 += __shfl_xor_sync(0xffffffffu, sum1, 1);
        sum1 += __shfl_xor_sync(0xffffffffu, sum1, 2);
        l0 = l0 * sc0 + sum0;
        l1 = l1 * sc1 + sum1;
        #pragma unroll
        for (int nt = 0; nt < 8; nt++) {
            oacc[nt][0] *= sc0; oacc[nt][1] *= sc0;
            oacc[nt][2] *= sc1; oacc[nt][3] *= sc1;
        }

        // all warps done reading K from KPs -> reuse as P tile
        __syncthreads();
        #pragma unroll
        for (int nt = 0; nt < 8; nt++) {
            KPs[wm + g][nt * 8 + 2 * t4]         = f2tff(sacc[nt][0]);
            KPs[wm + g][nt * 8 + 2 * t4 + 1]     = f2tff(sacc[nt][1]);
            KPs[wm + g + 8][nt * 8 + 2 * t4]     = f2tff(sacc[nt][2]);
            KPs[wm + g + 8][nt * 8 + 2 * t4 + 1] = f2tff(sacc[nt][3]);
        }
        __syncwarp();  // each warp PV-reads only its own P rows

        // O += P . V
        #pragma unroll
        for (int k8 = 0; k8 < 8; k8++) {
            int kk = k8 * 8;
            unsigned af[4];
            af[0] = __float_as_uint(KPs[wm + g][kk + t4]);
            af[1] = __float_as_uint(KPs[wm + g + 8][kk + t4]);
            af[2] = __float_as_uint(KPs[wm + g][kk + t4 + 4]);
            af[3] = __float_as_uint(KPs[wm + g + 8][kk + t4 + 4]);
            #pragma unroll
            for (int nt = 0; nt < 8; nt++) {
                unsigned bf[2];
                bf[0] = __float_as_uint(Vs[kk + t4][nt * 8 + g]);
                bf[1] = __float_as_uint(Vs[kk + t4 + 4][nt * 8 + g]);
                mma_tf32(oacc[nt], af, bf);
            }
        }
    }

    // write output
    float inv0 = 1.f / l0, inv1 = 1.f / l1;
    #pragma unroll
    for (int nt = 0; nt < 8; nt++) {
        int col = h * DKH + nt * 8 + 2 * t4;
        if (gi0 < SEQ)
            *(float2*)&g_att[(size_t)(b * SEQ + gi0) * DM + col] =
                make_float2(oacc[nt][0] * inv0, oacc[nt][1] * inv0);
        if (gi1 < SEQ)
            *(float2*)&g_att[(size_t)(b * SEQ + gi1) * DM + col] =
                make_float2(oacc[nt][2] * inv1, oacc[nt][3] * inv1);
    }
}

// ---------------- residual add + LayerNorm -----------------------------------
__global__ void ln_kernel(const float* __restrict__ fc, const float* __restrict__ resid,
                          const float* __restrict__ gamma, const float* __restrict__ beta,
                          float* __restrict__ out) {
    const int row = blockIdx.x;
    const float* f = fc + (size_t)row * DM;
    const float* rsd = resid + (size_t)row * DM;
    float x[3], s = 0.f, s2 = 0.f;
    #pragma unroll
    for (int t = 0; t < 3; t++) {
        int c = threadIdx.x + t * 256;
        float v = f[c] + rsd[c];
        x[t] = v; s += v; s2 += v * v;
    }
    __shared__ float r1[8], r2[8];
    #pragma unroll
    for (int o = 16; o; o >>= 1) {
        s  += __shfl_xor_sync(0xffffffffu, s, o);
        s2 += __shfl_xor_sync(0xffffffffu, s2, o);
    }
    if ((threadIdx.x & 31) == 0) { r1[threadIdx.x >> 5] = s; r2[threadIdx.x >> 5] = s2; }
    __syncthreads();
    __shared__ float smu, srstd;
    if (threadIdx.x < 8) {
        float a = r1[threadIdx.x], bsum = r2[threadIdx.x];
        #pragma unroll
        for (int o = 4; o; o >>= 1) {
            a    += __shfl_xor_sync(0xffu, a, o);
            bsum += __shfl_xor_sync(0xffu, bsum, o);
        }
        if (threadIdx.x == 0) {
            float mu = a * (1.f / DM);
            float var = bsum * (1.f / DM) - mu * mu;
            smu = mu;
            srstd = rsqrtf(var + 1e-6f);
        }
    }
    __syncthreads();
    float mu = smu, rstd = srstd;
    #pragma unroll
    for (int t = 0; t < 3; t++) {
        int c = threadIdx.x + t * 256;
        out[(size_t)row * DM + c] = (x[t] - mu) * rstd * gamma[c] + beta[c];
    }
}

// ---------------- launch ------------------------------------------------------
extern "C" void kernel_launch(void* const* d_in, const int* in_sizes, int n_in,
                              void* d_out, int out_size) {
    const float* q     = (const float*)d_in[0];
    const float* k     = (const float*)d_in[1];
    const float* v     = (const float*)d_in[2];
    const float* pos   = (const float*)d_in[3];
    const float* emb   = (const float*)d_in[4];
    const float* w_qs  = (const float*)d_in[5];
    const float* w_ks  = (const float*)d_in[6];
    const float* w_vs  = (const float*)d_in[7];
    const float* w_fc  = (const float*)d_in[8];
    const float* gamma = (const float*)d_in[9];
    const float* beta  = (const float*)d_in[10];
    float* out = (float*)d_out;

    float *Qp, *Kp, *Vp, *att;
    cudaGetSymbolAddress((void**)&Qp,  g_Q);
    cudaGetSymbolAddress((void**)&Kp,  g_K);
    cudaGetSymbolAddress((void**)&Vp,  g_V);
    cudaGetSymbolAddress((void**)&att, g_att);

    const int M = BATCH * SEQ;  // 9232
    dim3 gg(6, (M + 127) / 128);
    tgemm_768<<<gg, 256>>>(q, w_qs, Qp, M);
    tgemm_768<<<gg, 256>>>(k, w_ks, Kp, M);
    tgemm_768<<<gg, 256>>>(v, w_vs, Vp, M);

    rnorm_kernel<<<dim3(NP, BATCH), 256>>>(emb);
    penalty_mma<<<dim3(5, 5, BATCH), 256>>>(pos);

    attn_mma<<<dim3((SEQ + 63) / 64, NH, BATCH), 128>>>();

    tgemm_768<<<gg, 256>>>(att, w_fc, Qp, M);  // reuse g_Q for FC output
    ln_kernel<<<M, 256>>>(Qp, q, gamma, beta, out);
}

// round 15
// speedup vs baseline: 1.0004x; 1.0004x over previous
#include <cuda_runtime.h>
#include <math_constants.h>

#define BATCH 16
#define SEQ   577
#define DM    768
#define NH    12
#define DKH   64
#define NP    576   // SEQ - 1 (patch tokens)

// ---------------- scratch (allocation-free per harness rules) ----------------
__device__ float g_Q[BATCH * SEQ * DM];    // Q projection, later reused for FC output
__device__ float g_K[BATCH * SEQ * DM];
__device__ float g_V[BATCH * SEQ * DM];
__device__ float g_att[BATCH * SEQ * DM];  // attention output (head-merged)
__device__ float g_pen[(size_t)BATCH * NP * NP];
__device__ float g_En[(size_t)BATCH * NP * DM];  // normalized embeddings (tf32)

__device__ __forceinline__ unsigned f2tf(float x) {
    unsigned u;
    asm("cvt.rna.tf32.f32 %0, %1;" : "=r"(u) : "f"(x));
    return u;
}
__device__ __forceinline__ float f2tff(float x) { return __uint_as_float(f2tf(x)); }

__device__ __forceinline__ void mma_tf32(float* d, const unsigned* a, const unsigned* b) {
    asm volatile(
        "mma.sync.aligned.m16n8k8.row.col.f32.tf32.tf32.f32 "
        "{%0,%1,%2,%3},{%4,%5,%6,%7},{%8,%9},{%0,%1,%2,%3};"
        : "+f"(d[0]), "+f"(d[1]), "+f"(d[2]), "+f"(d[3])
        : "r"(a[0]), "r"(a[1]), "r"(a[2]), "r"(a[3]), "r"(b[0]), "r"(b[1]));
}

// ---------------- tf32 tensor-core GEMM: C[M,768] = A[M,768] @ W[768,768] -----
__global__ __launch_bounds__(256, 2)
void tgemm_768(const float* __restrict__ A, const float* __restrict__ W,
               float* __restrict__ C, int M) {
    __shared__ float As[128][36];
    __shared__ float Bs[32][132];
    const int tid = threadIdx.x;
    const int wid = tid >> 5, lane = tid & 31;
    const int g = lane >> 2, t4 = lane & 3;
    const int wm = (wid >> 2) * 64, wn = (wid & 3) * 32;
    const int row0 = blockIdx.y * 128, col0 = blockIdx.x * 128;

    float acc[4][4][4] = {};
    const int arow = tid >> 1, acol = (tid & 1) * 16;
    const int brow = tid >> 3, bcol = (tid & 7) * 16;

    for (int k0 = 0; k0 < 768; k0 += 32) {
        const int gr = row0 + arow;
        #pragma unroll
        for (int i = 0; i < 4; i++) {
            float4 v = (gr < M) ? *(const float4*)&A[(size_t)gr * 768 + k0 + acol + i * 4]
                                : make_float4(0.f, 0.f, 0.f, 0.f);
            v.x = f2tff(v.x); v.y = f2tff(v.y); v.z = f2tff(v.z); v.w = f2tff(v.w);
            *(float4*)&As[arow][acol + i * 4] = v;
        }
        #pragma unroll
        for (int i = 0; i < 4; i++) {
            float4 v = *(const float4*)&W[(size_t)(k0 + brow) * 768 + col0 + bcol + i * 4];
            v.x = f2tff(v.x); v.y = f2tff(v.y); v.z = f2tff(v.z); v.w = f2tff(v.w);
            *(float4*)&Bs[brow][bcol + i * 4] = v;
        }
        __syncthreads();

        #pragma unroll
        for (int kk = 0; kk < 32; kk += 8) {
            unsigned af[4][4], bf[4][2];
            #pragma unroll
            for (int mt = 0; mt < 4; mt++) {
                int r = wm + mt * 16;
                af[mt][0] = __float_as_uint(As[r + g][kk + t4]);
                af[mt][1] = __float_as_uint(As[r + g + 8][kk + t4]);
                af[mt][2] = __float_as_uint(As[r + g][kk + t4 + 4]);
                af[mt][3] = __float_as_uint(As[r + g + 8][kk + t4 + 4]);
            }
            #pragma unroll
            for (int nt = 0; nt < 4; nt++) {
                int c = wn + nt * 8;
                bf[nt][0] = __float_as_uint(Bs[kk + t4][c + g]);
                bf[nt][1] = __float_as_uint(Bs[kk + t4 + 4][c + g]);
            }
            #pragma unroll
            for (int mt = 0; mt < 4; mt++)
                #pragma unroll
                for (int nt = 0; nt < 4; nt++)
                    mma_tf32(acc[mt][nt], af[mt], bf[nt]);
        }
        __syncthreads();
    }

    #pragma unroll
    for (int mt = 0; mt < 4; mt++) {
        #pragma unroll
        for (int nt = 0; nt < 4; nt++) {
            int r = row0 + wm + mt * 16 + g;
            int c = col0 + wn + nt * 8 + 2 * t4;
            if (r < M)
                *(float2*)&C[(size_t)r * 768 + c] = make_float2(acc[mt][nt][0], acc[mt][nt][1]);
            if (r + 8 < M)
                *(float2*)&C[(size_t)(r + 8) * 768 + c] = make_float2(acc[mt][nt][2], acc[mt][nt][3]);
        }
    }
}

// ---------------- normalize embedding rows -> tf32 buffer --------------------
__global__ void rnorm_kernel(const float* __restrict__ emb) {
    int b = blockIdx.y, i = blockIdx.x;
    const float* row = emb + (size_t)(b * SEQ + 1 + i) * DM;
    float x[3], s = 0.f;
    #pragma unroll
    for (int t = 0; t < 3; t++) {
        x[t] = row[threadIdx.x + t * 256];
        s += x[t] * x[t];
    }
    __shared__ float red[8];
    #pragma unroll
    for (int o = 16; o; o >>= 1) s += __shfl_xor_sync(0xffffffffu, s, o);
    if ((threadIdx.x & 31) == 0) red[threadIdx.x >> 5] = s;
    __syncthreads();
    __shared__ float srn;
    if (threadIdx.x < 8) {
        float v = red[threadIdx.x];
        #pragma unroll
        for (int o = 4; o; o >>= 1) v += __shfl_xor_sync(0xffu, v, o);
        if (threadIdx.x == 0) srn = rsqrtf(v + 1e-12f);
    }
    __syncthreads();
    float rn = srn;
    float* dst = g_En + (size_t)(b * NP + i) * DM;
    #pragma unroll
    for (int t = 0; t < 3; t++)
        dst[threadIdx.x + t * 256] = f2tff(x[t] * rn);
}

// ---------------- penalty = (En . En^T) * dist, via tf32 MMA -----------------
__global__ __launch_bounds__(256, 2)
void penalty_mma(const float* __restrict__ pos) {
    __shared__ float Es[128][36];
    __shared__ float Fs[128][36];
    const int b = blockIdx.z;
    const int tid = threadIdx.x;
    const int wid = tid >> 5, lane = tid & 31;
    const int g = lane >> 2, t4 = lane & 3;
    const int wm = (wid >> 2) * 64, wn = (wid & 3) * 32;
    const int i0 = blockIdx.y * 128, j0 = blockIdx.x * 128;
    const float* En = g_En + (size_t)b * NP * DM;

    float acc[4][4][4] = {};
    const int lrow = tid >> 1, lcol = (tid & 1) * 16;

    for (int k0 = 0; k0 < 768; k0 += 32) {
        #pragma unroll
        for (int i = 0; i < 4; i++) {
            int ir = i0 + lrow;
            float4 v = (ir < NP) ? *(const float4*)&En[(size_t)ir * 768 + k0 + lcol + i * 4]
                                 : make_float4(0.f, 0.f, 0.f, 0.f);
            *(float4*)&Es[lrow][lcol + i * 4] = v;
            int jr = j0 + lrow;
            float4 w = (jr < NP) ? *(const float4*)&En[(size_t)jr * 768 + k0 + lcol + i * 4]
                                 : make_float4(0.f, 0.f, 0.f, 0.f);
            *(float4*)&Fs[lrow][lcol + i * 4] = w;
        }
        __syncthreads();

        #pragma unroll
        for (int kk = 0; kk < 32; kk += 8) {
            unsigned af[4][4], bf[4][2];
            #pragma unroll
            for (int mt = 0; mt < 4; mt++) {
                int r = wm + mt * 16;
                af[mt][0] = __float_as_uint(Es[r + g][kk + t4]);
                af[mt][1] = __float_as_uint(Es[r + g + 8][kk + t4]);
                af[mt][2] = __float_as_uint(Es[r + g][kk + t4 + 4]);
                af[mt][3] = __float_as_uint(Es[r + g + 8][kk + t4 + 4]);
            }
            #pragma unroll
            for (int nt = 0; nt < 4; nt++) {
                int c = wn + nt * 8;
                bf[nt][0] = __float_as_uint(Fs[c + g][kk + t4]);
                bf[nt][1] = __float_as_uint(Fs[c + g][kk + t4 + 4]);
            }
            #pragma unroll
            for (int mt = 0; mt < 4; mt++)
                #pragma unroll
                for (int nt = 0; nt < 4; nt++)
                    mma_tf32(acc[mt][nt], af[mt], bf[nt]);
        }
        __syncthreads();
    }

    #pragma unroll
    for (int mt = 0; mt < 4; mt++) {
        #pragma unroll
        for (int rr = 0; rr < 2; rr++) {
            int i = i0 + wm + mt * 16 + g + rr * 8;
            if (i >= NP) continue;
            float pix = pos[((size_t)b * NP + i) * 2 + 0];
            float piy = pos[((size_t)b * NP + i) * 2 + 1];
            #pragma unroll
            for (int nt = 0; nt < 4; nt++) {
                #pragma unroll
                for (int cc = 0; cc < 2; cc++) {
                    int j = j0 + wn + nt * 8 + 2 * t4 + cc;
                    if (j >= NP) continue;
                    float dx = pix - pos[((size_t)b * NP + j) * 2 + 0];
                    float dy = piy - pos[((size_t)b * NP + j) * 2 + 1];
                    float dist = sqrtf(dx * dx + dy * dy + 1e-12f);
                    g_pen[((size_t)b * NP + i) * NP + j] = acc[mt][nt][rr * 2 + cc] * dist;
                }
            }
        }
    }
}

// ---------------- tensor-core flash attention with penalty bias --------------
// 4 warps, BM=64 (warp owns 16 rows), BN=64 key tile, D=64.
// KPs holds the K tile, then is reused as the P tile (barrier-protected).
__global__ __launch_bounds__(128)
void attn_mma() {
    __shared__ float KPs[64][68];
    __shared__ float Vs[64][68];

    const int b = blockIdx.z, h = blockIdx.y, i0 = blockIdx.x * 64;
    const int tid = threadIdx.x;
    const int wid = tid >> 5, lane = tid & 31;
    const int g = lane >> 2, t4 = lane & 3;
    const int wm = wid * 16;

    // ---- prologue: stage Q tile in Vs, hoist A-fragments to registers ----
    for (int t = tid; t < 1024; t += 128) {
        int row = t >> 4, c4 = (t & 15) * 4;
        int gi = i0 + row;
        float4 v = make_float4(0.f, 0.f, 0.f, 0.f);
        if (gi < SEQ) v = *(const float4*)&g_Q[(size_t)(b * SEQ + gi) * DM + h * DKH + c4];
        v.x = f2tff(v.x); v.y = f2tff(v.y); v.z = f2tff(v.z); v.w = f2tff(v.w);
        *(float4*)&Vs[row][c4] = v;
    }
    __syncthreads();
    unsigned qf[8][4];
    #pragma unroll
    for (int k8 = 0; k8 < 8; k8++) {
        int kk = k8 * 8;
        qf[k8][0] = __float_as_uint(Vs[wm + g][kk + t4]);
        qf[k8][1] = __float_as_uint(Vs[wm + g + 8][kk + t4]);
        qf[k8][2] = __float_as_uint(Vs[wm + g][kk + t4 + 4]);
        qf[k8][3] = __float_as_uint(Vs[wm + g + 8][kk + t4 + 4]);
    }

    float oacc[8][4] = {};
    float m0 = -CUDART_INF_F, m1 = -CUDART_INF_F, l0 = 0.f, l1 = 0.f;
    const int gi0 = i0 + wm + g, gi1 = gi0 + 8;
    const bool p0 = (gi0 >= 1 && gi0 < SEQ);
    const bool p1 = (gi1 < SEQ);  // gi1 >= 8 always
    const float* pen0 = g_pen + ((size_t)b * NP + (gi0 - 1)) * NP;
    const float* pen1 = g_pen + ((size_t)b * NP + (gi1 - 1)) * NP;

    const int NT = (SEQ + 63) / 64;  // 10
    for (int jt = 0; jt < NT; jt++) {
        const int j0 = jt * 64;
        __syncthreads();  // protect KPs/Vs from previous-iter readers (and qf at jt=0)
        for (int t = tid; t < 1024; t += 128) {
            int row = t >> 4, c4 = (t & 15) * 4;
            int gj = j0 + row;
            float4 kv = make_float4(0.f, 0.f, 0.f, 0.f);
            float4 vv = make_float4(0.f, 0.f, 0.f, 0.f);
            if (gj < SEQ) {
                kv = *(const float4*)&g_K[(size_t)(b * SEQ + gj) * DM + h * DKH + c4];
                vv = *(const float4*)&g_V[(size_t)(b * SEQ + gj) * DM + h * DKH + c4];
            }
            kv.x = f2tff(kv.x); kv.y = f2tff(kv.y); kv.z = f2tff(kv.z); kv.w = f2tff(kv.w);
            vv.x = f2tff(vv.x); vv.y = f2tff(vv.y); vv.z = f2tff(vv.z); vv.w = f2tff(vv.w);
            *(float4*)&KPs[row][c4] = kv;
            *(float4*)&Vs[row][c4] = vv;
        }
        __syncthreads();

        // S = Q . K^T (warp's 16 rows x 64 cols)
        float sacc[8][4] = {};
        #pragma unroll
        for (int k8 = 0; k8 < 8; k8++) {
            int kk = k8 * 8;
            #pragma unroll
            for (int nt = 0; nt < 8; nt++) {
                unsigned bf[2];
                bf[0] = __float_as_uint(KPs[nt * 8 + g][kk + t4]);
                bf[1] = __float_as_uint(KPs[nt * 8 + g][kk + t4 + 4]);
                mma_tf32(sacc[nt], qf[k8], bf);
            }
        }

        // epilogue: scale, penalty, mask; row maxima
        float mloc0 = -CUDART_INF_F, mloc1 = -CUDART_INF_F;
        #pragma unroll
        for (int nt = 0; nt < 8; nt++) {
            #pragma unroll
            for (int cc = 0; cc < 2; cc++) {
                int gj = j0 + nt * 8 + 2 * t4 + cc;
                float v0 = sacc[nt][cc] * 0.125f;
                float v1 = sacc[nt][2 + cc] * 0.125f;
                if (gj >= 1 && gj < SEQ) {
                    if (p0) v0 -= __ldg(&pen0[gj - 1]);
                    if (p1) v1 -= __ldg(&pen1[gj - 1]);
                }
                if (gj >= SEQ) { v0 = -CUDART_INF_F; v1 = -CUDART_INF_F; }
                sacc[nt][cc] = v0; sacc[nt][2 + cc] = v1;
                mloc0 = fmaxf(mloc0, v0); mloc1 = fmaxf(mloc1, v1);
            }
        }
        mloc0 = fmaxf(mloc0, __shfl_xor_sync(0xffffffffu, mloc0, 1));
        mloc0 = fmaxf(mloc0, __shfl_xor_sync(0xffffffffu, mloc0, 2));
        mloc1 = fmaxf(mloc1, __shfl_xor_sync(0xffffffffu, mloc1, 1));
        mloc1 = fmaxf(mloc1, __shfl_xor_sync(0xffffffffu, mloc1, 2));
        float mn0 = fmaxf(m0, mloc0), mn1 = fmaxf(m1, mloc1);
        float sc0 = __expf(m0 - mn0), sc1 = __expf(m1 - mn1);
        m0 = mn0; m1 = mn1;

        float sum0 = 0.f, sum1 = 0.f;
        #pragma unroll
        for (int nt = 0; nt < 8; nt++) {
            #pragma unroll
            for (int cc = 0; cc < 2; cc++) {
                float e0 = __expf(sacc[nt][cc] - m0);
                float e1 = __expf(sacc[nt][2 + cc] - m1);
                sum0 += e0; sum1 += e1;
                sacc[nt][cc] = e0; sacc[nt][2 + cc] = e1;
            }
        }
        sum0 += __shfl_xor_sync(0xffffffffu, sum0, 1);
        sum0 += __shfl_xor_sync(0xffffffffu, sum0, 2);
        sum1 += __shfl_xor_sync(0xffffffffu, sum1, 1);
        sum1 += __shfl_xor_sync(0xffffffffu, sum1, 2);
        l0 = l0 * sc0 + sum0;
        l1 = l1 * sc1 + sum1;
        #pragma unroll
        for (int nt = 0; nt < 8; nt++) {
            oacc[nt][0] *= sc0; oacc[nt][1] *= sc0;
            oacc[nt][2] *= sc1; oacc[nt][3] *= sc1;
        }

        // all warps done reading K from KPs -> reuse as P tile
        __syncthreads();
        #pragma unroll
        for (int nt = 0; nt < 8; nt++) {
            KPs[wm + g][nt * 8 + 2 * t4]         = f2tff(sacc[nt][0]);
            KPs[wm + g][nt * 8 + 2 * t4 + 1]     = f2tff(sacc[nt][1]);
            KPs[wm + g + 8][nt * 8 + 2 * t4]     = f2tff(sacc[nt][2]);
            KPs[wm + g + 8][nt * 8 + 2 * t4 + 1] = f2tff(sacc[nt][3]);
        }
        __syncwarp();  // each warp PV-reads only its own P rows

        // O += P . V
        #pragma unroll
        for (int k8 = 0; k8 < 8; k8++) {
            int kk = k8 * 8;
            unsigned af[4];
            af[0] = __float_as_uint(KPs[wm + g][kk + t4]);
            af[1] = __float_as_uint(KPs[wm + g + 8][kk + t4]);
            af[2] = __float_as_uint(KPs[wm + g][kk + t4 + 4]);
            af[3] = __float_as_uint(KPs[wm + g + 8][kk + t4 + 4]);
            #pragma unroll
            for (int nt = 0; nt < 8; nt++) {
                unsigned bf[2];
                bf[0] = __float_as_uint(Vs[kk + t4][nt * 8 + g]);
                bf[1] = __float_as_uint(Vs[kk + t4 + 4][nt * 8 + g]);
                mma_tf32(oacc[nt], af, bf);
            }
        }
    }

    // write output
    float inv0 = 1.f / l0, inv1 = 1.f / l1;
    #pragma unroll
    for (int nt = 0; nt < 8; nt++) {
        int col = h * DKH + nt * 8 + 2 * t4;
        if (gi0 < SEQ)
            *(float2*)&g_att[(size_t)(b * SEQ + gi0) * DM + col] =
                make_float2(oacc[nt][0] * inv0, oacc[nt][1] * inv0);
        if (gi1 < SEQ)
            *(float2*)&g_att[(size_t)(b * SEQ + gi1) * DM + col] =
                make_float2(oacc[nt][2] * inv1, oacc[nt][3] * inv1);
    }
}

// ---------------- residual add + LayerNorm -----------------------------------
__global__ void ln_kernel(const float* __restrict__ fc, const float* __restrict__ resid,
                          const float* __restrict__ gamma, const float* __restrict__ beta,
                          float* __restrict__ out) {
    const int row = blockIdx.x;
    const float* f = fc + (size_t)row * DM;
    const float* rsd = resid + (size_t)row * DM;
    float x[3], s = 0.f, s2 = 0.f;
    #pragma unroll
    for (int t = 0; t < 3; t++) {
        int c = threadIdx.x + t * 256;
        float v = f[c] + rsd[c];
        x[t] = v; s += v; s2 += v * v;
    }
    __shared__ float r1[8], r2[8];
    #pragma unroll
    for (int o = 16; o; o >>= 1) {
        s  += __shfl_xor_sync(0xffffffffu, s, o);
        s2 += __shfl_xor_sync(0xffffffffu, s2, o);
    }
    if ((threadIdx.x & 31) == 0) { r1[threadIdx.x >> 5] = s; r2[threadIdx.x >> 5] = s2; }
    __syncthreads();
    __shared__ float smu, srstd;
    if (threadIdx.x < 8) {
        float a = r1[threadIdx.x], bsum = r2[threadIdx.x];
        #pragma unroll
        for (int o = 4; o; o >>= 1) {
            a    += __shfl_xor_sync(0xffu, a, o);
            bsum += __shfl_xor_sync(0xffu, bsum, o);
        }
        if (threadIdx.x == 0) {
            float mu = a * (1.f / DM);
            float var = bsum * (1.f / DM) - mu * mu;
            smu = mu;
            srstd = rsqrtf(var + 1e-6f);
        }
    }
    __syncthreads();
    float mu = smu, rstd = srstd;
    #pragma unroll
    for (int t = 0; t < 3; t++) {
        int c = threadIdx.x + t * 256;
        out[(size_t)row * DM + c] = (x[t] - mu) * rstd * gamma[c] + beta[c];
    }
}

// ---------------- launch ------------------------------------------------------
extern "C" void kernel_launch(void* const* d_in, const int* in_sizes, int n_in,
                              void* d_out, int out_size) {
    const float* q     = (const float*)d_in[0];
    const float* k     = (const float*)d_in[1];
    const float* v     = (const float*)d_in[2];
    const float* pos   = (const float*)d_in[3];
    const float* emb   = (const float*)d_in[4];
    const float* w_qs  = (const float*)d_in[5];
    const float* w_ks  = (const float*)d_in[6];
    const float* w_vs  = (const float*)d_in[7];
    const float* w_fc  = (const float*)d_in[8];
    const float* gamma = (const float*)d_in[9];
    const float* beta  = (const float*)d_in[10];
    float* out = (float*)d_out;

    float *Qp, *Kp, *Vp, *att;
    cudaGetSymbolAddress((void**)&Qp,  g_Q);
    cudaGetSymbolAddress((void**)&Kp,  g_K);
    cudaGetSymbolAddress((void**)&Vp,  g_V);
    cudaGetSymbolAddress((void**)&att, g_att);

    const int M = BATCH * SEQ;  // 9232
    dim3 gg(6, (M + 127) / 128);
    tgemm_768<<<gg, 256>>>(q, w_qs, Qp, M);
    tgemm_768<<<gg, 256>>>(k, w_ks, Kp, M);
    tgemm_768<<<gg, 256>>>(v, w_vs, Vp, M);

    rnorm_kernel<<<dim3(NP, BATCH), 256>>>(emb);
    penalty_mma<<<dim3(5, 5, BATCH), 256>>>(pos);

    attn_mma<<<dim3((SEQ + 63) / 64, NH, BATCH), 128>>>();

    tgemm_768<<<gg, 256>>>(att, w_fc, Qp, M);  // reuse g_Q for FC output
    ln_kernel<<<M, 256>>>(Qp, q, gamma, beta, out);
}

// round 16
// speedup vs baseline: 1.0058x; 1.0055x over previous
#include <cuda_runtime.h>
#include <math_constants.h>

#define BATCH 16
#define SEQ   577
#define DM    768
#define NH    12
#define DKH   64
#define NP    576   // SEQ - 1 (patch tokens)

// ---------------- scratch (allocation-free per harness rules) ----------------
__device__ float g_Q[BATCH * SEQ * DM];    // Q projection, later reused for FC output
__device__ float g_K[BATCH * SEQ * DM];
__device__ float g_V[BATCH * SEQ * DM];
__device__ float g_att[BATCH * SEQ * DM];  // attention output (head-merged)
__device__ float g_pen[(size_t)BATCH * NP * NP];
__device__ float g_En[(size_t)BATCH * NP * DM];  // normalized embeddings (tf32)

__device__ __forceinline__ unsigned f2tf(float x) {
    unsigned u;
    asm("cvt.rna.tf32.f32 %0, %1;" : "=r"(u) : "f"(x));
    return u;
}
__device__ __forceinline__ float f2tff(float x) { return __uint_as_float(f2tf(x)); }

__device__ __forceinline__ void mma_tf32(float* d, const unsigned* a, const unsigned* b) {
    asm volatile(
        "mma.sync.aligned.m16n8k8.row.col.f32.tf32.tf32.f32 "
        "{%0,%1,%2,%3},{%4,%5,%6,%7},{%8,%9},{%0,%1,%2,%3};"
        : "+f"(d[0]), "+f"(d[1]), "+f"(d[2]), "+f"(d[3])
        : "r"(a[0]), "r"(a[1]), "r"(a[2]), "r"(a[3]), "r"(b[0]), "r"(b[1]));
}

// ---------------- tf32 tensor-core GEMM: C[M,768] = A[M,768] @ W[768,768] -----
__global__ __launch_bounds__(256, 2)
void tgemm_768(const float* __restrict__ A, const float* __restrict__ W,
               float* __restrict__ C, int M) {
    __shared__ float As[128][36];
    __shared__ float Bs[32][132];
    const int tid = threadIdx.x;
    const int wid = tid >> 5, lane = tid & 31;
    const int g = lane >> 2, t4 = lane & 3;
    const int wm = (wid >> 2) * 64, wn = (wid & 3) * 32;
    const int row0 = blockIdx.y * 128, col0 = blockIdx.x * 128;

    float acc[4][4][4] = {};
    const int arow = tid >> 1, acol = (tid & 1) * 16;
    const int brow = tid >> 3, bcol = (tid & 7) * 16;

    for (int k0 = 0; k0 < 768; k0 += 32) {
        const int gr = row0 + arow;
        #pragma unroll
        for (int i = 0; i < 4; i++) {
            float4 v = (gr < M) ? *(const float4*)&A[(size_t)gr * 768 + k0 + acol + i * 4]
                                : make_float4(0.f, 0.f, 0.f, 0.f);
            v.x = f2tff(v.x); v.y = f2tff(v.y); v.z = f2tff(v.z); v.w = f2tff(v.w);
            *(float4*)&As[arow][acol + i * 4] = v;
        }
        #pragma unroll
        for (int i = 0; i < 4; i++) {
            float4 v = *(const float4*)&W[(size_t)(k0 + brow) * 768 + col0 + bcol + i * 4];
            v.x = f2tff(v.x); v.y = f2tff(v.y); v.z = f2tff(v.z); v.w = f2tff(v.w);
            *(float4*)&Bs[brow][bcol + i * 4] = v;
        }
        __syncthreads();

        #pragma unroll
        for (int kk = 0; kk < 32; kk += 8) {
            unsigned af[4][4], bf[4][2];
            #pragma unroll
            for (int mt = 0; mt < 4; mt++) {
                int r = wm + mt * 16;
                af[mt][0] = __float_as_uint(As[r + g][kk + t4]);
                af[mt][1] = __float_as_uint(As[r + g + 8][kk + t4]);
                af[mt][2] = __float_as_uint(As[r + g][kk + t4 + 4]);
                af[mt][3] = __float_as_uint(As[r + g + 8][kk + t4 + 4]);
            }
            #pragma unroll
            for (int nt = 0; nt < 4; nt++) {
                int c = wn + nt * 8;
                bf[nt][0] = __float_as_uint(Bs[kk + t4][c + g]);
                bf[nt][1] = __float_as_uint(Bs[kk + t4 + 4][c + g]);
            }
            #pragma unroll
            for (int mt = 0; mt < 4; mt++)
                #pragma unroll
                for (int nt = 0; nt < 4; nt++)
                    mma_tf32(acc[mt][nt], af[mt], bf[nt]);
        }
        __syncthreads();
    }

    #pragma unroll
    for (int mt = 0; mt < 4; mt++) {
        #pragma unroll
        for (int nt = 0; nt < 4; nt++) {
            int r = row0 + wm + mt * 16 + g;
            int c = col0 + wn + nt * 8 + 2 * t4;
            if (r < M)
                *(float2*)&C[(size_t)r * 768 + c] = make_float2(acc[mt][nt][0], acc[mt][nt][1]);
            if (r + 8 < M)
                *(float2*)&C[(size_t)(r + 8) * 768 + c] = make_float2(acc[mt][nt][2], acc[mt][nt][3]);
        }
    }
}

// ---------------- normalize embedding rows -> tf32 buffer --------------------
__global__ void rnorm_kernel(const float* __restrict__ emb) {
    int b = blockIdx.y, i = blockIdx.x;
    const float* row = emb + (size_t)(b * SEQ + 1 + i) * DM;
    float x[3], s = 0.f;
    #pragma unroll
    for (int t = 0; t < 3; t++) {
        x[t] = row[threadIdx.x + t * 256];
        s += x[t] * x[t];
    }
    __shared__ float red[8];
    #pragma unroll
    for (int o = 16; o; o >>= 1) s += __shfl_xor_sync(0xffffffffu, s, o);
    if ((threadIdx.x & 31) == 0) red[threadIdx.x >> 5] = s;
    __syncthreads();
    __shared__ float srn;
    if (threadIdx.x < 8) {
        float v = red[threadIdx.x];
        #pragma unroll
        for (int o = 4; o; o >>= 1) v += __shfl_xor_sync(0xffu, v, o);
        if (threadIdx.x == 0) srn = rsqrtf(v + 1e-12f);
    }
    __syncthreads();
    float rn = srn;
    float* dst = g_En + (size_t)(b * NP + i) * DM;
    #pragma unroll
    for (int t = 0; t < 3; t++)
        dst[threadIdx.x + t * 256] = f2tff(x[t] * rn);
}

// ---------------- penalty = (En . En^T) * dist, via tf32 MMA -----------------
__global__ __launch_bounds__(256, 2)
void penalty_mma(const float* __restrict__ pos) {
    __shared__ float Es[128][36];
    __shared__ float Fs[128][36];
    const int b = blockIdx.z;
    const int tid = threadIdx.x;
    const int wid = tid >> 5, lane = tid & 31;
    const int g = lane >> 2, t4 = lane & 3;
    const int wm = (wid >> 2) * 64, wn = (wid & 3) * 32;
    const int i0 = blockIdx.y * 128, j0 = blockIdx.x * 128;
    const float* En = g_En + (size_t)b * NP * DM;

    float acc[4][4][4] = {};
    const int lrow = tid >> 1, lcol = (tid & 1) * 16;

    for (int k0 = 0; k0 < 768; k0 += 32) {
        #pragma unroll
        for (int i = 0; i < 4; i++) {
            int ir = i0 + lrow;
            float4 v = (ir < NP) ? *(const float4*)&En[(size_t)ir * 768 + k0 + lcol + i * 4]
                                 : make_float4(0.f, 0.f, 0.f, 0.f);
            *(float4*)&Es[lrow][lcol + i * 4] = v;
            int jr = j0 + lrow;
            float4 w = (jr < NP) ? *(const float4*)&En[(size_t)jr * 768 + k0 + lcol + i * 4]
                                 : make_float4(0.f, 0.f, 0.f, 0.f);
            *(float4*)&Fs[lrow][lcol + i * 4] = w;
        }
        __syncthreads();

        #pragma unroll
        for (int kk = 0; kk < 32; kk += 8) {
            unsigned af[4][4], bf[4][2];
            #pragma unroll
            for (int mt = 0; mt < 4; mt++) {
                int r = wm + mt * 16;
                af[mt][0] = __float_as_uint(Es[r + g][kk + t4]);
                af[mt][1] = __float_as_uint(Es[r + g + 8][kk + t4]);
                af[mt][2] = __float_as_uint(Es[r + g][kk + t4 + 4]);
                af[mt][3] = __float_as_uint(Es[r + g + 8][kk + t4 + 4]);
            }
            #pragma unroll
            for (int nt = 0; nt < 4; nt++) {
                int c = wn + nt * 8;
                bf[nt][0] = __float_as_uint(Fs[c + g][kk + t4]);
                bf[nt][1] = __float_as_uint(Fs[c + g][kk + t4 + 4]);
            }
            #pragma unroll
            for (int mt = 0; mt < 4; mt++)
                #pragma unroll
                for (int nt = 0; nt < 4; nt++)
                    mma_tf32(acc[mt][nt], af[mt], bf[nt]);
        }
        __syncthreads();
    }

    #pragma unroll
    for (int mt = 0; mt < 4; mt++) {
        #pragma unroll
        for (int rr = 0; rr < 2; rr++) {
            int i = i0 + wm + mt * 16 + g + rr * 8;
            if (i >= NP) continue;
            float pix = pos[((size_t)b * NP + i) * 2 + 0];
            float piy = pos[((size_t)b * NP + i) * 2 + 1];
            #pragma unroll
            for (int nt = 0; nt < 4; nt++) {
                #pragma unroll
                for (int cc = 0; cc < 2; cc++) {
                    int j = j0 + wn + nt * 8 + 2 * t4 + cc;
                    if (j >= NP) continue;
                    float dx = pix - pos[((size_t)b * NP + j) * 2 + 0];
                    float dy = piy - pos[((size_t)b * NP + j) * 2 + 1];
                    float dist = sqrtf(dx * dx + dy * dy + 1e-12f);
                    g_pen[((size_t)b * NP + i) * NP + j] = acc[mt][nt][rr * 2 + cc] * dist;
                }
            }
        }
    }
}

// ---------------- tensor-core flash attention with penalty bias --------------
// 4 warps, BM=64 (warp owns 16 rows), BN=64 key tile, D=64.
// KPs holds the K tile, then is reused as the P tile (barrier-protected).
__global__ __launch_bounds__(128)
void attn_mma() {
    __shared__ float KPs[64][68];
    __shared__ float Vs[64][68];

    const int b = blockIdx.z, h = blockIdx.y, i0 = blockIdx.x * 64;
    const int tid = threadIdx.x;
    const int wid = tid >> 5, lane = tid & 31;
    const int g = lane >> 2, t4 = lane & 3;
    const int wm = wid * 16;

    // ---- prologue: stage Q tile in Vs, hoist A-fragments to registers ----
    for (int t = tid; t < 1024; t += 128) {
        int row = t >> 4, c4 = (t & 15) * 4;
        int gi = i0 + row;
        float4 v = make_float4(0.f, 0.f, 0.f, 0.f);
        if (gi < SEQ) v = *(const float4*)&g_Q[(size_t)(b * SEQ + gi) * DM + h * DKH + c4];
        v.x = f2tff(v.x); v.y = f2tff(v.y); v.z = f2tff(v.z); v.w = f2tff(v.w);
        *(float4*)&Vs[row][c4] = v;
    }
    __syncthreads();
    unsigned qf[8][4];
    #pragma unroll
    for (int k8 = 0; k8 < 8; k8++) {
        int kk = k8 * 8;
        qf[k8][0] = __float_as_uint(Vs[wm + g][kk + t4]);
        qf[k8][1] = __float_as_uint(Vs[wm + g + 8][kk + t4]);
        qf[k8][2] = __float_as_uint(Vs[wm + g][kk + t4 + 4]);
        qf[k8][3] = __float_as_uint(Vs[wm + g + 8][kk + t4 + 4]);
    }

    float oacc[8][4] = {};
    float m0 = -CUDART_INF_F, m1 = -CUDART_INF_F, l0 = 0.f, l1 = 0.f;
    const int gi0 = i0 + wm + g, gi1 = gi0 + 8;
    const bool p0 = (gi0 >= 1 && gi0 < SEQ);
    const bool p1 = (gi1 < SEQ);  // gi1 >= 8 always
    const float* pen0 = g_pen + ((size_t)b * NP + (gi0 - 1)) * NP;
    const float* pen1 = g_pen + ((size_t)b * NP + (gi1 - 1)) * NP;

    const int NT = (SEQ + 63) / 64;  // 10
    for (int jt = 0; jt < NT; jt++) {
        const int j0 = jt * 64;
        __syncthreads();  // protect KPs/Vs from previous-iter readers (and qf at jt=0)
        for (int t = tid; t < 1024; t += 128) {
            int row = t >> 4, c4 = (t & 15) * 4;
            int gj = j0 + row;
            float4 kv = make_float4(0.f, 0.f, 0.f, 0.f);
            float4 vv = make_float4(0.f, 0.f, 0.f, 0.f);
            if (gj < SEQ) {
                kv = *(const float4*)&g_K[(size_t)(b * SEQ + gj) * DM + h * DKH + c4];
                vv = *(const float4*)&g_V[(size_t)(b * SEQ + gj) * DM + h * DKH + c4];
            }
            kv.x = f2tff(kv.x); kv.y = f2tff(kv.y); kv.z = f2tff(kv.z); kv.w = f2tff(kv.w);
            vv.x = f2tff(vv.x); vv.y = f2tff(vv.y); vv.z = f2tff(vv.z); vv.w = f2tff(vv.w);
            *(float4*)&KPs[row][c4] = kv;
            *(float4*)&Vs[row][c4] = vv;
        }
        __syncthreads();

        // S = Q . K^T (warp's 16 rows x 64 cols)
        float sacc[8][4] = {};
        #pragma unroll
        for (int k8 = 0; k8 < 8; k8++) {
            int kk = k8 * 8;
            #pragma unroll
            for (int nt = 0; nt < 8; nt++) {
                unsigned bf[2];
                bf[0] = __float_as_uint(KPs[nt * 8 + g][kk + t4]);
                bf[1] = __float_as_uint(KPs[nt * 8 + g][kk + t4 + 4]);
                mma_tf32(sacc[nt], qf[k8], bf);
            }
        }

        // epilogue: scale, penalty, mask; row maxima
        float mloc0 = -CUDART_INF_F, mloc1 = -CUDART_INF_F;
        #pragma unroll
        for (int nt = 0; nt < 8; nt++) {
            #pragma unroll
            for (int cc = 0; cc < 2; cc++) {
                int gj = j0 + nt * 8 + 2 * t4 + cc;
                float v0 = sacc[nt][cc] * 0.125f;
                float v1 = sacc[nt][2 + cc] * 0.125f;
                if (gj >= 1 && gj < SEQ) {
                    if (p0) v0 -= __ldg(&pen0[gj - 1]);
                    if (p1) v1 -= __ldg(&pen1[gj - 1]);
                }
                if (gj >= SEQ) { v0 = -CUDART_INF_F; v1 = -CUDART_INF_F; }
                sacc[nt][cc] = v0; sacc[nt][2 + cc] = v1;
                mloc0 = fmaxf(mloc0, v0); mloc1 = fmaxf(mloc1, v1);
            }
        }
        mloc0 = fmaxf(mloc0, __shfl_xor_sync(0xffffffffu, mloc0, 1));
        mloc0 = fmaxf(mloc0, __shfl_xor_sync(0xffffffffu, mloc0, 2));
        mloc1 = fmaxf(mloc1, __shfl_xor_sync(0xffffffffu, mloc1, 1));
        mloc1 = fmaxf(mloc1, __shfl_xor_sync(0xffffffffu, mloc1, 2));
        float mn0 = fmaxf(m0, mloc0), mn1 = fmaxf(m1, mloc1);
        float sc0 = __expf(m0 - mn0), sc1 = __expf(m1 - mn1);
        m0 = mn0; m1 = mn1;

        float sum0 = 0.f, sum1 = 0.f;
        #pragma unroll
        for (int nt = 0; nt < 8; nt++) {
            #pragma unroll
            for (int cc = 0; cc < 2; cc++) {
                float e0 = __expf(sacc[nt][cc] - m0);
                float e1 = __expf(sacc[nt][2 + cc] - m1);
                sum0 += e0; sum1 += e1;
                sacc[nt][cc] = e0; sacc[nt][2 + cc] = e1;
            }
        }
        sum0 += __shfl_xor_sync(0xffffffffu, sum0, 1);
        sum0 += __shfl_xor_sync(0xffffffffu, sum0, 2);
        sum1 += __shfl_xor_sync(0xffffffffu, sum1, 1);
        sum1 += __shfl_xor_sync(0xffffffffu, sum1, 2);
        l0 = l0 * sc0 + sum0;
        l1 = l1 * sc1 + sum1;
        #pragma unroll
        for (int nt = 0; nt < 8; nt++) {
            oacc[nt][0] *= sc0; oacc[nt][1] *= sc0;
            oacc[nt][2] *= sc1; oacc[nt][3] *= sc1;
        }

        // all warps done reading K from KPs -> reuse as P tile
        __syncthreads();
        #pragma unroll
        for (int nt = 0; nt < 8; nt++) {
            KPs[wm + g][nt * 8 + 2 * t4]         = f2tff(sacc[nt][0]);
            KPs[wm + g][nt * 8 + 2 * t4 + 1]     = f2tff(sacc[nt][1]);
            KPs[wm + g + 8][nt * 8 + 2 * t4]     = f2tff(sacc[nt][2]);
            KPs[wm + g + 8][nt * 8 + 2 * t4 + 1] = f2tff(sacc[nt][3]);
        }
        __syncwarp();  // each warp PV-reads only its own P rows

        // O += P . V
        #pragma unroll
        for (int k8 = 0; k8 < 8; k8++) {
            int kk = k8 * 8;
            unsigned af[4];
            af[0] = __float_as_uint(KPs[wm + g][kk + t4]);
            af[1] = __float_as_uint(KPs[wm + g + 8][kk + t4]);
            af[2] = __float_as_uint(KPs[wm + g][kk + t4 + 4]);
            af[3] = __float_as_uint(KPs[wm + g + 8][kk + t4 + 4]);
            #pragma unroll
            for (int nt = 0; nt < 8; nt++) {
                unsigned bf[2];
                bf[0] = __float_as_uint(Vs[kk + t4][nt * 8 + g]);
                bf[1] = __float_as_uint(Vs[kk + t4 + 4][nt * 8 + g]);
                mma_tf32(oacc[nt], af, bf);
            }
        }
    }

    // write output
    float inv0 = 1.f / l0, inv1 = 1.f / l1;
    #pragma unroll
    for (int nt = 0; nt < 8; nt++) {
        int col = h * DKH + nt * 8 + 2 * t4;
        if (gi0 < SEQ)
            *(float2*)&g_att[(size_t)(b * SEQ + gi0) * DM + col] =
                make_float2(oacc[nt][0] * inv0, oacc[nt][1] * inv0);
        if (gi1 < SEQ)
            *(float2*)&g_att[(size_t)(b * SEQ + gi1) * DM + col] =
                make_float2(oacc[nt][2] * inv1, oacc[nt][3] * inv1);
    }
}

// ---------------- residual add + LayerNorm -----------------------------------
__global__ void ln_kernel(const float* __restrict__ fc, const float* __restrict__ resid,
                          const float* __restrict__ gamma, const float* __restrict__ beta,
                          float* __restrict__ out) {
    const int row = blockIdx.x;
    const float* f = fc + (size_t)row * DM;
    const float* rsd = resid + (size_t)row * DM;
    float x[3], s = 0.f, s2 = 0.f;
    #pragma unroll
    for (int t = 0; t < 3; t++) {
        int c = threadIdx.x + t * 256;
        float v = f[c] + rsd[c];
        x[t] = v; s += v; s2 += v * v;
    }
    __shared__ float r1[8], r2[8];
    #pragma unroll
    for (int o = 16; o; o >>= 1) {
        s  += __shfl_xor_sync(0xffffffffu, s, o);
        s2 += __shfl_xor_sync(0xffffffffu, s2, o);
    }
    if ((threadIdx.x & 31) == 0) { r1[threadIdx.x >> 5] = s; r2[threadIdx.x >> 5] = s2; }
    __syncthreads();
    __shared__ float smu, srstd;
    if (threadIdx.x < 8) {
        float a = r1[threadIdx.x], bsum = r2[threadIdx.x];
        #pragma unroll
        for (int o = 4; o; o >>= 1) {
            a    += __shfl_xor_sync(0xffu, a, o);
            bsum += __shfl_xor_sync(0xffu, bsum, o);
        }
        if (threadIdx.x == 0) {
            float mu = a * (1.f / DM);
            float var = bsum * (1.f / DM) - mu * mu;
            smu = mu;
            srstd = rsqrtf(var + 1e-6f);
        }
    }
    __syncthreads();
    float mu = smu, rstd = srstd;
    #pragma unroll
    for (int t = 0; t < 3; t++) {
        int c = threadIdx.x + t * 256;
        out[(size_t)row * DM + c] = (x[t] - mu) * rstd * gamma[c] + beta[c];
    }
}

// ---------------- launch ------------------------------------------------------
extern "C" void kernel_launch(void* const* d_in, const int* in_sizes, int n_in,
                              void* d_out, int out_size) {
    const float* q     = (const float*)d_in[0];
    const float* k     = (const float*)d_in[1];
    const float* v     = (const float*)d_in[2];
    const float* pos   = (const float*)d_in[3];
    const float* emb   = (const float*)d_in[4];
    const float* w_qs  = (const float*)d_in[5];
    const float* w_ks  = (const float*)d_in[6];
    const float* w_vs  = (const float*)d_in[7];
    const float* w_fc  = (const float*)d_in[8];
    const float* gamma = (const float*)d_in[9];
    const float* beta  = (const float*)d_in[10];
    float* out = (float*)d_out;

    float *Qp, *Kp, *Vp, *att;
    cudaGetSymbolAddress((void**)&Qp,  g_Q);
    cudaGetSymbolAddress((void**)&Kp,  g_K);
    cudaGetSymbolAddress((void**)&Vp,  g_V);
    cudaGetSymbolAddress((void**)&att, g_att);

    const int M = BATCH * SEQ;  // 9232
    dim3 gg(6, (M + 127) / 128);
    tgemm_768<<<gg, 256>>>(q, w_qs, Qp, M);
    tgemm_768<<<gg, 256>>>(k, w_ks, Kp, M);
    tgemm_768<<<gg, 256>>>(v, w_vs, Vp, M);

    rnorm_kernel<<<dim3(NP, BATCH), 256>>>(emb);
    penalty_mma<<<dim3(5, 5, BATCH), 256>>>(pos);

    attn_mma<<<dim3((SEQ + 63) / 64, NH, BATCH), 128>>>();

    tgemm_768<<<gg, 256>>>(att, w_fc, Qp, M);  // reuse g_Q for FC output
    ln_kernel<<<M, 256>>>(Qp, q, gamma, beta, out);
}

// round 17
// speedup vs baseline: 1.0060x; 1.0002x over previous
#include <cuda_runtime.h>
#include <math_constants.h>

#define BATCH 16
#define SEQ   577
#define DM    768
#define NH    12
#define DKH   64
#define NP    576   // SEQ - 1 (patch tokens)

// ---------------- scratch (allocation-free per harness rules) ----------------
__device__ float g_Q[BATCH * SEQ * DM];    // Q projection, later reused for FC output
__device__ float g_K[BATCH * SEQ * DM];
__device__ float g_V[BATCH * SEQ * DM];
__device__ float g_att[BATCH * SEQ * DM];  // attention output (head-merged)
__device__ float g_pen[(size_t)BATCH * NP * NP];
__device__ float g_En[(size_t)BATCH * NP * DM];  // normalized embeddings (tf32)

__device__ __forceinline__ unsigned f2tf(float x) {
    unsigned u;
    asm("cvt.rna.tf32.f32 %0, %1;" : "=r"(u) : "f"(x));
    return u;
}
__device__ __forceinline__ float f2tff(float x) { return __uint_as_float(f2tf(x)); }

__device__ __forceinline__ void mma_tf32(float* d, const unsigned* a, const unsigned* b) {
    asm volatile(
        "mma.sync.aligned.m16n8k8.row.col.f32.tf32.tf32.f32 "
        "{%0,%1,%2,%3},{%4,%5,%6,%7},{%8,%9},{%0,%1,%2,%3};"
        : "+f"(d[0]), "+f"(d[1]), "+f"(d[2]), "+f"(d[3])
        : "r"(a[0]), "r"(a[1]), "r"(a[2]), "r"(a[3]), "r"(b[0]), "r"(b[1]));
}

// ---------------- tf32 tensor-core GEMM: C[M,768] = A[M,768] @ W[768,768] -----
__global__ __launch_bounds__(256, 2)
void tgemm_768(const float* __restrict__ A, const float* __restrict__ W,
               float* __restrict__ C, int M) {
    __shared__ float As[128][36];
    __shared__ float Bs[32][132];
    const int tid = threadIdx.x;
    const int wid = tid >> 5, lane = tid & 31;
    const int g = lane >> 2, t4 = lane & 3;
    const int wm = (wid >> 2) * 64, wn = (wid & 3) * 32;
    const int row0 = blockIdx.y * 128, col0 = blockIdx.x * 128;

    float acc[4][4][4] = {};
    const int arow = tid >> 1, acol = (tid & 1) * 16;
    const int brow = tid >> 3, bcol = (tid & 7) * 16;

    for (int k0 = 0; k0 < 768; k0 += 32) {
        const int gr = row0 + arow;
        #pragma unroll
        for (int i = 0; i < 4; i++) {
            float4 v = (gr < M) ? *(const float4*)&A[(size_t)gr * 768 + k0 + acol + i * 4]
                                : make_float4(0.f, 0.f, 0.f, 0.f);
            v.x = f2tff(v.x); v.y = f2tff(v.y); v.z = f2tff(v.z); v.w = f2tff(v.w);
            *(float4*)&As[arow][acol + i * 4] = v;
        }
        #pragma unroll
        for (int i = 0; i < 4; i++) {
            float4 v = *(const float4*)&W[(size_t)(k0 + brow) * 768 + col0 + bcol + i * 4];
            v.x = f2tff(v.x); v.y = f2tff(v.y); v.z = f2tff(v.z); v.w = f2tff(v.w);
            *(float4*)&Bs[brow][bcol + i * 4] = v;
        }
        __syncthreads();

        #pragma unroll
        for (int kk = 0; kk < 32; kk += 8) {
            unsigned af[4][4], bf[4][2];
            #pragma unroll
            for (int mt = 0; mt < 4; mt++) {
                int r = wm + mt * 16;
                af[mt][0] = __float_as_uint(As[r + g][kk + t4]);
                af[mt][1] = __float_as_uint(As[r + g + 8][kk + t4]);
                af[mt][2] = __float_as_uint(As[r + g][kk + t4 + 4]);
                af[mt][3] = __float_as_uint(As[r + g + 8][kk + t4 + 4]);
            }
            #pragma unroll
            for (int nt = 0; nt < 4; nt++) {
                int c = wn + nt * 8;
                bf[nt][0] = __float_as_uint(Bs[kk + t4][c + g]);
                bf[nt][1] = __float_as_uint(Bs[kk + t4 + 4][c + g]);
            }
            #pragma unroll
            for (int mt = 0; mt < 4; mt++)
                #pragma unroll
                for (int nt = 0; nt < 4; nt++)
                    mma_tf32(acc[mt][nt], af[mt], bf[nt]);
        }
        __syncthreads();
    }

    #pragma unroll
    for (int mt = 0; mt < 4; mt++) {
        #pragma unroll
        for (int nt = 0; nt < 4; nt++) {
            int r = row0 + wm + mt * 16 + g;
            int c = col0 + wn + nt * 8 + 2 * t4;
            if (r < M)
                *(float2*)&C[(size_t)r * 768 + c] = make_float2(acc[mt][nt][0], acc[mt][nt][1]);
            if (r + 8 < M)
                *(float2*)&C[(size_t)(r + 8) * 768 + c] = make_float2(acc[mt][nt][2], acc[mt][nt][3]);
        }
    }
}

// ---------------- normalize embedding rows -> tf32 buffer --------------------
__global__ void rnorm_kernel(const float* __restrict__ emb) {
    int b = blockIdx.y, i = blockIdx.x;
    const float* row = emb + (size_t)(b * SEQ + 1 + i) * DM;
    float x[3], s = 0.f;
    #pragma unroll
    for (int t = 0; t < 3; t++) {
        x[t] = row[threadIdx.x + t * 256];
        s += x[t] * x[t];
    }
    __shared__ float red[8];
    #pragma unroll
    for (int o = 16; o; o >>= 1) s += __shfl_xor_sync(0xffffffffu, s, o);
    if ((threadIdx.x & 31) == 0) red[threadIdx.x >> 5] = s;
    __syncthreads();
    __shared__ float srn;
    if (threadIdx.x < 8) {
        float v = red[threadIdx.x];
        #pragma unroll
        for (int o = 4; o; o >>= 1) v += __shfl_xor_sync(0xffu, v, o);
        if (threadIdx.x == 0) srn = rsqrtf(v + 1e-12f);
    }
    __syncthreads();
    float rn = srn;
    float* dst = g_En + (size_t)(b * NP + i) * DM;
    #pragma unroll
    for (int t = 0; t < 3; t++)
        dst[threadIdx.x + t * 256] = f2tff(x[t] * rn);
}

// ---------------- penalty = (En . En^T) * dist, via tf32 MMA -----------------
__global__ __launch_bounds__(256, 2)
void penalty_mma(const float* __restrict__ pos) {
    __shared__ float Es[128][36];
    __shared__ float Fs[128][36];
    const int b = blockIdx.z;
    const int tid = threadIdx.x;
    const int wid = tid >> 5, lane = tid & 31;
    const int g = lane >> 2, t4 = lane & 3;
    const int wm = (wid >> 2) * 64, wn = (wid & 3) * 32;
    const int i0 = blockIdx.y * 128, j0 = blockIdx.x * 128;
    const float* En = g_En + (size_t)b * NP * DM;

    float acc[4][4][4] = {};
    const int lrow = tid >> 1, lcol = (tid & 1) * 16;

    for (int k0 = 0; k0 < 768; k0 += 32) {
        #pragma unroll
        for (int i = 0; i < 4; i++) {
            int ir = i0 + lrow;
            float4 v = (ir < NP) ? *(const float4*)&En[(size_t)ir * 768 + k0 + lcol + i * 4]
                                 : make_float4(0.f, 0.f, 0.f, 0.f);
            *(float4*)&Es[lrow][lcol + i * 4] = v;
            int jr = j0 + lrow;
            float4 w = (jr < NP) ? *(const float4*)&En[(size_t)jr * 768 + k0 + lcol + i * 4]
                                 : make_float4(0.f, 0.f, 0.f, 0.f);
            *(float4*)&Fs[lrow][lcol + i * 4] = w;
        }
        __syncthreads();

        #pragma unroll
        for (int kk = 0; kk < 32; kk += 8) {
            unsigned af[4][4], bf[4][2];
            #pragma unroll
            for (int mt = 0; mt < 4; mt++) {
                int r = wm + mt * 16;
                af[mt][0] = __float_as_uint(Es[r + g][kk + t4]);
                af[mt][1] = __float_as_uint(Es[r + g + 8][kk + t4]);
                af[mt][2] = __float_as_uint(Es[r + g][kk + t4 + 4]);
                af[mt][3] = __float_as_uint(Es[r + g + 8][kk + t4 + 4]);
            }
            #pragma unroll
            for (int nt = 0; nt < 4; nt++) {
                int c = wn + nt * 8;
                bf[nt][0] = __float_as_uint(Fs[c + g][kk + t4]);
                bf[nt][1] = __float_as_uint(Fs[c + g][kk + t4 + 4]);
            }
            #pragma unroll
            for (int mt = 0; mt < 4; mt++)
                #pragma unroll
                for (int nt = 0; nt < 4; nt++)
                    mma_tf32(acc[mt][nt], af[mt], bf[nt]);
        }
        __syncthreads();
    }

    #pragma unroll
    for (int mt = 0; mt < 4; mt++) {
        #pragma unroll
        for (int rr = 0; rr < 2; rr++) {
            int i = i0 + wm + mt * 16 + g + rr * 8;
            if (i >= NP) continue;
            float pix = pos[((size_t)b * NP + i) * 2 + 0];
            float piy = pos[((size_t)b * NP + i) * 2 + 1];
            #pragma unroll
            for (int nt = 0; nt < 4; nt++) {
                #pragma unroll
                for (int cc = 0; cc < 2; cc++) {
                    int j = j0 + wn + nt * 8 + 2 * t4 + cc;
                    if (j >= NP) continue;
                    float dx = pix - pos[((size_t)b * NP + j) * 2 + 0];
                    float dy = piy - pos[((size_t)b * NP + j) * 2 + 1];
                    float dist = sqrtf(dx * dx + dy * dy + 1e-12f);
                    g_pen[((size_t)b * NP + i) * NP + j] = acc[mt][nt][rr * 2 + cc] * dist;
                }
            }
        }
    }
}

// ---------------- tensor-core flash attention with penalty bias --------------
// 4 warps, BM=64 (warp owns 16 rows), BN=64 key tile, D=64.
// KPs holds the K tile, then is reused as the P tile (barrier-protected).
__global__ __launch_bounds__(128)
void attn_mma() {
    __shared__ float KPs[64][68];
    __shared__ float Vs[64][68];

    const int b = blockIdx.z, h = blockIdx.y, i0 = blockIdx.x * 64;
    const int tid = threadIdx.x;
    const int wid = tid >> 5, lane = tid & 31;
    const int g = lane >> 2, t4 = lane & 3;
    const int wm = wid * 16;

    // ---- prologue: stage Q tile in Vs, hoist A-fragments to registers ----
    for (int t = tid; t < 1024; t += 128) {
        int row = t >> 4, c4 = (t & 15) * 4;
        int gi = i0 + row;
        float4 v = make_float4(0.f, 0.f, 0.f, 0.f);
        if (gi < SEQ) v = *(const float4*)&g_Q[(size_t)(b * SEQ + gi) * DM + h * DKH + c4];
        v.x = f2tff(v.x); v.y = f2tff(v.y); v.z = f2tff(v.z); v.w = f2tff(v.w);
        *(float4*)&Vs[row][c4] = v;
    }
    __syncthreads();
    unsigned qf[8][4];
    #pragma unroll
    for (int k8 = 0; k8 < 8; k8++) {
        int kk = k8 * 8;
        qf[k8][0] = __float_as_uint(Vs[wm + g][kk + t4]);
        qf[k8][1] = __float_as_uint(Vs[wm + g + 8][kk + t4]);
        qf[k8][2] = __float_as_uint(Vs[wm + g][kk + t4 + 4]);
        qf[k8][3] = __float_as_uint(Vs[wm + g + 8][kk + t4 + 4]);
    }

    float oacc[8][4] = {};
    float m0 = -CUDART_INF_F, m1 = -CUDART_INF_F, l0 = 0.f, l1 = 0.f;
    const int gi0 = i0 + wm + g, gi1 = gi0 + 8;
    const bool p0 = (gi0 >= 1 && gi0 < SEQ);
    const bool p1 = (gi1 < SEQ);  // gi1 >= 8 always
    const float* pen0 = g_pen + ((size_t)b * NP + (gi0 - 1)) * NP;
    const float* pen1 = g_pen + ((size_t)b * NP + (gi1 - 1)) * NP;

    const int NT = (SEQ + 63) / 64;  // 10
    for (int jt = 0; jt < NT; jt++) {
        const int j0 = jt * 64;
        __syncthreads();  // protect KPs/Vs from previous-iter readers (and qf at jt=0)
        for (int t = tid; t < 1024; t += 128) {
            int row = t >> 4, c4 = (t & 15) * 4;
            int gj = j0 + row;
            float4 kv = make_float4(0.f, 0.f, 0.f, 0.f);
            float4 vv = make_float4(0.f, 0.f, 0.f, 0.f);
            if (gj < SEQ) {
                kv = *(const float4*)&g_K[(size_t)(b * SEQ + gj) * DM + h * DKH + c4];
                vv = *(const float4*)&g_V[(size_t)(b * SEQ + gj) * DM + h * DKH + c4];
            }
            kv.x = f2tff(kv.x); kv.y = f2tff(kv.y); kv.z = f2tff(kv.z); kv.w = f2tff(kv.w);
            vv.x = f2tff(vv.x); vv.y = f2tff(vv.y); vv.z = f2tff(vv.z); vv.w = f2tff(vv.w);
            *(float4*)&KPs[row][c4] = kv;
            *(float4*)&Vs[row][c4] = vv;
        }
        __syncthreads();

        // S = Q . K^T (warp's 16 rows x 64 cols)
        float sacc[8][4] = {};
        #pragma unroll
        for (int k8 = 0; k8 < 8; k8++) {
            int kk = k8 * 8;
            #pragma unroll
            for (int nt = 0; nt < 8; nt++) {
                unsigned bf[2];
                bf[0] = __float_as_uint(KPs[nt * 8 + g][kk + t4]);
                bf[1] = __float_as_uint(KPs[nt * 8 + g][kk + t4 + 4]);
                mma_tf32(sacc[nt], qf[k8], bf);
            }
        }

        // epilogue: scale, penalty, mask; row maxima
        float mloc0 = -CUDART_INF_F, mloc1 = -CUDART_INF_F;
        #pragma unroll
        for (int nt = 0; nt < 8; nt++) {
            #pragma unroll
            for (int cc = 0; cc < 2; cc++) {
                int gj = j0 + nt * 8 + 2 * t4 + cc;
                float v0 = sacc[nt][cc] * 0.125f;
                float v1 = sacc[nt][2 + cc] * 0.125f;
                if (gj >= 1 && gj < SEQ) {
                    if (p0) v0 -= __ldg(&pen0[gj - 1]);
                    if (p1) v1 -= __ldg(&pen1[gj - 1]);
                }
                if (gj >= SEQ) { v0 = -CUDART_INF_F; v1 = -CUDART_INF_F; }
                sacc[nt][cc] = v0; sacc[nt][2 + cc] = v1;
                mloc0 = fmaxf(mloc0, v0); mloc1 = fmaxf(mloc1, v1);
            }
        }
        mloc0 = fmaxf(mloc0, __shfl_xor_sync(0xffffffffu, mloc0, 1));
        mloc0 = fmaxf(mloc0, __shfl_xor_sync(0xffffffffu, mloc0, 2));
        mloc1 = fmaxf(mloc1, __shfl_xor_sync(0xffffffffu, mloc1, 1));
        mloc1 = fmaxf(mloc1, __shfl_xor_sync(0xffffffffu, mloc1, 2));
        float mn0 = fmaxf(m0, mloc0), mn1 = fmaxf(m1, mloc1);
        float sc0 = __expf(m0 - mn0), sc1 = __expf(m1 - mn1);
        m0 = mn0; m1 = mn1;

        float sum0 = 0.f, sum1 = 0.f;
        #pragma unroll
        for (int nt = 0; nt < 8; nt++) {
            #pragma unroll
            for (int cc = 0; cc < 2; cc++) {
                float e0 = __expf(sacc[nt][cc] - m0);
                float e1 = __expf(sacc[nt][2 + cc] - m1);
                sum0 += e0; sum1 += e1;
                sacc[nt][cc] = e0; sacc[nt][2 + cc] = e1;
            }
        }
        sum0 += __shfl_xor_sync(0xffffffffu, sum0, 1);
        sum0 += __shfl_xor_sync(0xffffffffu, sum0, 2);
        sum1 += __shfl_xor_sync(0xffffffffu, sum1, 1);
        sum1 += __shfl_xor_sync(0xffffffffu, sum1, 2);
        l0 = l0 * sc0 + sum0;
        l1 = l1 * sc1 + sum1;
        #pragma unroll
        for (int nt = 0; nt < 8; nt++) {
            oacc[nt][0] *= sc0; oacc[nt][1] *= sc0;
            oacc[nt][2] *= sc1; oacc[nt][3] *= sc1;
        }

        // all warps done reading K from KPs -> reuse as P tile
        __syncthreads();
        #pragma unroll
        for (int nt = 0; nt < 8; nt++) {
            KPs[wm + g][nt * 8 + 2 * t4]         = f2tff(sacc[nt][0]);
            KPs[wm + g][nt * 8 + 2 * t4 + 1]     = f2tff(sacc[nt][1]);
            KPs[wm + g + 8][nt * 8 + 2 * t4]     = f2tff(sacc[nt][2]);
            KPs[wm + g + 8][nt * 8 + 2 * t4 + 1] = f2tff(sacc[nt][3]);
        }
        __syncwarp();  // each warp PV-reads only its own P rows

        // O += P . V
        #pragma unroll
        for (int k8 = 0; k8 < 8; k8++) {
            int kk = k8 * 8;
            unsigned af[4];
            af[0] = __float_as_uint(KPs[wm + g][kk + t4]);
            af[1] = __float_as_uint(KPs[wm + g + 8][kk + t4]);
            af[2] = __float_as_uint(KPs[wm + g][kk + t4 + 4]);
            af[3] = __float_as_uint(KPs[wm + g + 8][kk + t4 + 4]);
            #pragma unroll
            for (int nt = 0; nt < 8; nt++) {
                unsigned bf[2];
                bf[0] = __float_as_uint(Vs[kk + t4][nt * 8 + g]);
                bf[1] = __float_as_uint(Vs[kk + t4 + 4][nt * 8 + g]);
                mma_tf32(oacc[nt], af, bf);
            }
        }
    }

    // write output
    float inv0 = 1.f / l0, inv1 = 1.f / l1;
    #pragma unroll
    for (int nt = 0; nt < 8; nt++) {
        int col = h * DKH + nt * 8 + 2 * t4;
        if (gi0 < SEQ)
            *(float2*)&g_att[(size_t)(b * SEQ + gi0) * DM + col] =
                make_float2(oacc[nt][0] * inv0, oacc[nt][1] * inv0);
        if (gi1 < SEQ)
            *(float2*)&g_att[(size_t)(b * SEQ + gi1) * DM + col] =
                make_float2(oacc[nt][2] * inv1, oacc[nt][3] * inv1);
    }
}

// ---------------- residual add + LayerNorm -----------------------------------
__global__ void ln_kernel(const float* __restrict__ fc, const float* __restrict__ resid,
                          const float* __restrict__ gamma, const float* __restrict__ beta,
                          float* __restrict__ out) {
    const int row = blockIdx.x;
    const float* f = fc + (size_t)row * DM;
    const float* rsd = resid + (size_t)row * DM;
    float x[3], s = 0.f, s2 = 0.f;
    #pragma unroll
    for (int t = 0; t < 3; t++) {
        int c = threadIdx.x + t * 256;
        float v = f[c] + rsd[c];
        x[t] = v; s += v; s2 += v * v;
    }
    __shared__ float r1[8], r2[8];
    #pragma unroll
    for (int o = 16; o; o >>= 1) {
        s  += __shfl_xor_sync(0xffffffffu, s, o);
        s2 += __shfl_xor_sync(0xffffffffu, s2, o);
    }
    if ((threadIdx.x & 31) == 0) { r1[threadIdx.x >> 5] = s; r2[threadIdx.x >> 5] = s2; }
    __syncthreads();
    __shared__ float smu, srstd;
    if (threadIdx.x < 8) {
        float a = r1[threadIdx.x], bsum = r2[threadIdx.x];
        #pragma unroll
        for (int o = 4; o; o >>= 1) {
            a    += __shfl_xor_sync(0xffu, a, o);
            bsum += __shfl_xor_sync(0xffu, bsum, o);
        }
        if (threadIdx.x == 0) {
            float mu = a * (1.f / DM);
            float var = bsum * (1.f / DM) - mu * mu;
            smu = mu;
            srstd = rsqrtf(var + 1e-6f);
        }
    }
    __syncthreads();
    float mu = smu, rstd = srstd;
    #pragma unroll
    for (int t = 0; t < 3; t++) {
        int c = threadIdx.x + t * 256;
        out[(size_t)row * DM + c] = (x[t] - mu) * rstd * gamma[c] + beta[c];
    }
}

// ---------------- launch ------------------------------------------------------
extern "C" void kernel_launch(void* const* d_in, const int* in_sizes, int n_in,
                              void* d_out, int out_size) {
    const float* q     = (const float*)d_in[0];
    const float* k     = (const float*)d_in[1];
    const float* v     = (const float*)d_in[2];
    const float* pos   = (const float*)d_in[3];
    const float* emb   = (const float*)d_in[4];
    const float* w_qs  = (const float*)d_in[5];
    const float* w_ks  = (const float*)d_in[6];
    const float* w_vs  = (const float*)d_in[7];
    const float* w_fc  = (const float*)d_in[8];
    const float* gamma = (const float*)d_in[9];
    const float* beta  = (const float*)d_in[10];
    float* out = (float*)d_out;

    float *Qp, *Kp, *Vp, *att;
    cudaGetSymbolAddress((void**)&Qp,  g_Q);
    cudaGetSymbolAddress((void**)&Kp,  g_K);
    cudaGetSymbolAddress((void**)&Vp,  g_V);
    cudaGetSymbolAddress((void**)&att, g_att);

    const int M = BATCH * SEQ;  // 9232
    dim3 gg(6, (M + 127) / 128);
    tgemm_768<<<gg, 256>>>(q, w_qs, Qp, M);
    tgemm_768<<<gg, 256>>>(k, w_ks, Kp, M);
    tgemm_768<<<gg, 256>>>(v, w_vs, Vp, M);

    rnorm_kernel<<<dim3(NP, BATCH), 256>>>(emb);
    penalty_mma<<<dim3(5, 5, BATCH), 256>>>(pos);

    attn_mma<<<dim3((SEQ + 63) / 64, NH, BATCH), 128>>>();

    tgemm_768<<<gg, 256>>>(att, w_fc, Qp, M);  // reuse g_Q for FC output
    ln_kernel<<<M, 256>>>(Qp, q, gamma, beta, out);
}